// round 17
// baseline (speedup 1.0000x reference)
#include <cuda_runtime.h>
#include <math.h>
#include <stdint.h>

#define S_LEN   8192
#define E_DIM   1024
#define H_DIM   2048
#define T_TAGS  50

// ---------------- persistent recurrence config ----------------
#define RB_NBLK    128
#define RB_ROWS    16          // H rows per block (128*16 = 2048)
#define RB_THREADS 256         // 8 warps
#define N_GRP      8           // h chunks (one per warp)
#define GRP_CTAS   (RB_NBLK / N_GRP)    // 16 producer CTAs per chunk
#define CHUNK      (H_DIM / N_GRP)      // 256 floats per chunk

// ---------------- scratch (static device memory; no allocs) ----------------
__device__ float g_rnn[(size_t)S_LEN * H_DIM];   // 64 MB
__device__ unsigned g_cnt8[N_GRP * 32];          // 8 counters, 128B apart (R11-proven)

__global__ void init_cnt_kernel() {
    if (threadIdx.x < N_GRP * 32) g_cnt8[threadIdx.x] = 0u;
}

// ---------------- packed f32x2 helpers ----------------
__device__ __forceinline__ unsigned long long ffma2(unsigned long long a,
                                                    unsigned long long b,
                                                    unsigned long long c) {
    unsigned long long d;
    asm("fma.rn.f32x2 %0, %1, %2, %3;" : "=l"(d) : "l"(a), "l"(b), "l"(c));
    return d;
}
__device__ __forceinline__ unsigned long long addf2(unsigned long long a,
                                                    unsigned long long b) {
    unsigned long long d;
    asm("add.rn.f32x2 %0, %1, %2;" : "=l"(d) : "l"(a), "l"(b));
    return d;
}
// 64-bit shfl.xor via two 32-bit shfls
__device__ __forceinline__ unsigned long long shflx2(unsigned long long v,
                                                     int mask) {
    unsigned lo = (unsigned)v, hi = (unsigned)(v >> 32);
    lo = __shfl_xor_sync(0xffffffffu, lo, mask);
    hi = __shfl_xor_sync(0xffffffffu, hi, mask);
    return ((unsigned long long)hi << 32) | lo;
}

// fast tanh: 1 - 2/(e^{2x}+1); inf-safe, ~1e-6 rel err (budget is 1e-3)
__device__ __forceinline__ float tanh_fast(float x) {
    const float e2 = __expf(2.f * x);
    return 1.f - __fdividef(2.f, e2 + 1.f);
}

// ---------------- fused Kernel: recurrence + on-the-fly xi ----------------
// Recurrence path = R11 VERBATIM. xi computed in the poll-idle window, 2
// steps ahead (R16-proven). R17 delta: the FIRST acquire probe is issued
// BEFORE COMPUTE_XI so the xi compute overlaps the probe's L2 round trip
// instead of delaying discovery.
__global__ void __launch_bounds__(RB_THREADS, 1) rnn_kernel(
    const float* __restrict__ W_hh,
    const float* __restrict__ h0,
    const int*   __restrict__ sent,
    const float* __restrict__ emb,
    const float* __restrict__ W_ih,
    const float* __restrict__ b_ih,
    const float* __restrict__ b_hh)
{
    extern __shared__ float smem[];
    float* w_s    = smem;                    // [16][1024] W_ih slice, 64KB
    float* xi_buf = smem + 16384;            // [4][16] xi ring
    float* part   = smem + 16384 + 64;       // [2][8][16] partials

    const int b    = blockIdx.x;
    const int tid  = threadIdx.x;
    const int warp = tid >> 5;
    const int lane = tid & 31;
    const int row0 = b * RB_ROWS;

    // ---- stage W_ih slice into SMEM (contiguous 16384 floats) ----
    {
        const float4* src = (const float4*)(W_ih + (size_t)row0 * E_DIM);
        float4*       dst = (float4*)w_s;
#pragma unroll
        for (int i = 0; i < 16; i++)
            dst[tid + i * RB_THREADS] = src[tid + i * RB_THREADS];
    }

    // ---- W_hh registers: rows 0..15, cols warp*256 + lane*8 .. +7 ----
    unsigned long long W2[16][4];
    {
        const float* wb = W_hh + (size_t)row0 * H_DIM + warp * CHUNK + lane * 8;
#pragma unroll
        for (int r = 0; r < 16; r++) {
            ulonglong2 u = *(const ulonglong2*)(wb + (size_t)r * H_DIM);
            ulonglong2 v = *(const ulonglong2*)(wb + (size_t)r * H_DIM + 4);
            W2[r][0] = u.x; W2[r][1] = u.y; W2[r][2] = v.x; W2[r][3] = v.y;
        }
    }

    // ---- h registers init from h0 (this lane's 8 columns) ----
    unsigned long long h2[4];
    {
        const float* hp = h0 + warp * CHUNK + lane * 8;
        ulonglong2 u = *(const ulonglong2*)hp;
        ulonglong2 v = *(const ulonglong2*)(hp + 4);
        h2[0] = u.x; h2[1] = u.y; h2[2] = v.x; h2[3] = v.y;
    }

    // per-warp output-row biases (used by lane 0 only)
    const float bias0 = b_ih[row0 + 2 * warp]     + b_hh[row0 + 2 * warp];
    const float bias1 = b_ih[row0 + 2 * warp + 1] + b_hh[row0 + 2 * warp + 1];

    __syncthreads();   // w_s visible before any xi compute

#define COMPUTE_XI(ts)                                                        \
    do {                                                                      \
        const int _idx = __ldg(&sent[(ts)]);                                  \
        const float* _xr = emb + (size_t)_idx * E_DIM + lane * 4;             \
        const float* _w0 = w_s + (2 * warp) * E_DIM + lane * 4;               \
        const float* _w1 = w_s + (2 * warp + 1) * E_DIM + lane * 4;           \
        float _c00 = 0.f, _c01 = 0.f, _c10 = 0.f, _c11 = 0.f;                 \
        _Pragma("unroll")                                                     \
        for (int _k = 0; _k < 8; _k++) {                                      \
            const float4 _xv = __ldg((const float4*)(_xr + _k * 128));        \
            const float4 _wa = *(const float4*)(_w0 + _k * 128);              \
            const float4 _wb = *(const float4*)(_w1 + _k * 128);              \
            _c00 = fmaf(_wa.x, _xv.x, _c00); _c01 = fmaf(_wa.y, _xv.y, _c01); \
            _c00 = fmaf(_wa.z, _xv.z, _c00); _c01 = fmaf(_wa.w, _xv.w, _c01); \
            _c10 = fmaf(_wb.x, _xv.x, _c10); _c11 = fmaf(_wb.y, _xv.y, _c11); \
            _c10 = fmaf(_wb.z, _xv.z, _c10); _c11 = fmaf(_wb.w, _xv.w, _c11); \
        }                                                                     \
        float _a0 = _c00 + _c01, _a1 = _c10 + _c11;                           \
        unsigned long long _pa;                                               \
        asm("mov.b64 %0, {%1, %2};" : "=l"(_pa) : "f"(_a0), "f"(_a1));        \
        _pa = addf2(_pa, shflx2(_pa, 16));                                    \
        _pa = addf2(_pa, shflx2(_pa, 8));                                     \
        _pa = addf2(_pa, shflx2(_pa, 4));                                     \
        _pa = addf2(_pa, shflx2(_pa, 2));                                     \
        _pa = addf2(_pa, shflx2(_pa, 1));                                     \
        if (lane == 0) {                                                      \
            float _s0, _s1;                                                   \
            asm("mov.b64 {%0, %1}, %2;" : "=f"(_s0), "=f"(_s1) : "l"(_pa));   \
            xi_buf[((ts) & 3) * 16 + 2 * warp]     = _s0 + bias0;             \
            xi_buf[((ts) & 3) * 16 + 2 * warp + 1] = _s1 + bias1;             \
        }                                                                     \
    } while (0)

    // prologue: xi for steps 0 and 1
    COMPUTE_XI(0);
    COMPUTE_XI(1);
    __syncthreads();   // xi_buf[0],[1] visible (also pre-loop fence)

    unsigned* my_cnt   = &g_cnt8[(b >> 4) * 32];   // this CTA's group counter
    unsigned* poll_cnt = &g_cnt8[warp * 32];       // counter of chunk `warp`

    const bool q4 = (lane & 16) != 0;
    const bool q3 = (lane & 8)  != 0;
    const bool q2 = (lane & 4)  != 0;
    const bool q1 = (lane & 2)  != 0;

    for (int t = 0; t < S_LEN; t++) {
        const int buf = t & 1;

        // ---- matvec: 16 rows x 8 cols per lane, all in registers ----
        unsigned long long acc[16];
#pragma unroll
        for (int r = 0; r < 16; r++) {
            acc[r] = ffma2(W2[r][0], h2[0], 0ull);
            acc[r] = ffma2(W2[r][1], h2[1], acc[r]);
            acc[r] = ffma2(W2[r][2], h2[2], acc[r]);
            acc[r] = ffma2(W2[r][3], h2[3], acc[r]);
        }
        // fold k-halves, pack row pairs: q[j] = {row 2j, row 2j+1}
        unsigned long long q[8];
#pragma unroll
        for (int j = 0; j < 8; j++) {
            float l0, u0, l1, u1;
            asm("mov.b64 {%0, %1}, %2;" : "=f"(l0), "=f"(u0) : "l"(acc[2 * j]));
            asm("mov.b64 {%0, %1}, %2;" : "=f"(l1), "=f"(u1) : "l"(acc[2 * j + 1]));
            const float s0 = l0 + u0;
            const float s1 = l1 + u1;
            asm("mov.b64 %0, {%1, %2};" : "=l"(q[j]) : "f"(s0), "f"(s1));
        }

        // ---- halving-payload reduction: 9 shfls (R11-proven) ----
        unsigned long long n[4];
#pragma unroll
        for (int j = 0; j < 4; j++) {
            const unsigned long long keep = q4 ? q[j + 4] : q[j];
            const unsigned long long send = q4 ? q[j]     : q[j + 4];
            n[j] = addf2(keep, shflx2(send, 16));
        }
        unsigned long long m[2];
#pragma unroll
        for (int j = 0; j < 2; j++) {
            const unsigned long long keep = q3 ? n[j + 2] : n[j];
            const unsigned long long send = q3 ? n[j]     : n[j + 2];
            m[j] = addf2(keep, shflx2(send, 8));
        }
        unsigned long long p;
        {
            const unsigned long long keep = q2 ? m[1] : m[0];
            const unsigned long long send = q2 ? m[0] : m[1];
            p = addf2(keep, shflx2(send, 4));
        }
        float val;
        {
            float e, f;
            asm("mov.b64 {%0, %1}, %2;" : "=f"(e), "=f"(f) : "l"(p));
            const float keep = q1 ? f : e;
            const float send = q1 ? e : f;
            val = keep + __shfl_xor_sync(0xffffffffu, send, 2);
        }
        val += __shfl_xor_sync(0xffffffffu, val, 1);
        if ((lane & 1) == 0) part[(buf * N_GRP + warp) * 16 + (lane >> 1)] = val;

        __syncthreads();   // bar1: all partials of step t visible

        // ---- warp 0: cross-warp sum, tanh, coalesced publish, release ----
        if (warp == 0) {
            if (lane < 16) {
                const float* pb = part + buf * N_GRP * 16;
                const float s =
                    ((pb[0 * 16 + lane] + pb[1 * 16 + lane]) +
                     (pb[2 * 16 + lane] + pb[3 * 16 + lane])) +
                    ((pb[4 * 16 + lane] + pb[5 * 16 + lane]) +
                     (pb[6 * 16 + lane] + pb[7 * 16 + lane]));
                const float hn = tanh_fast(s + xi_buf[(t & 3) * 16 + lane]);
                __stcg(g_rnn + (size_t)t * H_DIM + row0 + lane, hn);
            }
            __syncwarp();   // warp0's 16 stores happen-before lane0's release
            if (lane == 0) {
                asm volatile("red.release.gpu.global.add.u32 [%0], %1;"
                             :: "l"(my_cnt), "r"(1u) : "memory");
            }
        }

        if (t + 1 < S_LEN) {
            const unsigned want = (unsigned)(GRP_CTAS * (t + 1));
            unsigned v;
            // issue the FIRST probe, then overlap xi(t+2) with its flight
            asm volatile("ld.acquire.gpu.global.u32 %0, [%1];"
                         : "=r"(v) : "l"(poll_cnt) : "memory");
            if (t + 2 < S_LEN) COMPUTE_XI(t + 2);
            while (v < want) {
                asm volatile("ld.acquire.gpu.global.u32 %0, [%1];"
                             : "=r"(v) : "l"(poll_cnt) : "memory");
            }

            // load this lane's 8 h values straight into registers (L1 bypass)
            const float* hp = g_rnn + (size_t)t * H_DIM + warp * CHUNK + lane * 8;
            uint4 A = __ldcg((const uint4*)hp);
            uint4 B = __ldcg((const uint4*)(hp + 4));
            h2[0] = ((unsigned long long)A.y << 32) | A.x;
            h2[1] = ((unsigned long long)A.w << 32) | A.z;
            h2[2] = ((unsigned long long)B.y << 32) | B.x;
            h2[3] = ((unsigned long long)B.w << 32) | B.z;
            // no bar2: part[] is double-buffered (R11-proven)
        }
    }
#undef COMPUTE_XI
}

// ---------------- Kernel 3: tag head + log_softmax ----------------
// R17: 256 threads, one (token, tag) dot per thread (tok = tid>>6,
// tag = tid&63) with 4-way ILP -> 4x thread-parallelism on the dots vs the
// 50/128-active R5 head (which ncu shows issue-bound at 17%).
#define OB_TOK     4
#define OB_THREADS 256

__global__ __launch_bounds__(OB_THREADS) void head_kernel(
    const float* __restrict__ W_out,
    const float* __restrict__ b_out,
    float*       __restrict__ out)
{
    __shared__ float shh[OB_TOK][H_DIM];
    __shared__ float ts[OB_TOK][64];

    const int tid = threadIdx.x;
    const int s0  = blockIdx.x * OB_TOK;

    {
        const float4* src = (const float4*)(g_rnn + (size_t)s0 * H_DIM);
        float4*       dst = (float4*)&shh[0][0];
        for (int i = tid; i < OB_TOK * H_DIM / 4; i += OB_THREADS) dst[i] = src[i];
    }
    __syncthreads();

    {
        const int j   = tid & 63;
        const int tok = tid >> 6;
        if (j < T_TAGS) {
            const float* w = W_out + (size_t)j * H_DIM;
            const float* h = &shh[tok][0];
            float a0 = 0.f, a1 = 0.f, a2 = 0.f, a3 = 0.f;
            for (int c = 0; c < H_DIM; c += 16) {
                float4 w0 = *(const float4*)(w + c);
                float4 h0 = *(const float4*)(h + c);
                float4 w1 = *(const float4*)(w + c + 4);
                float4 h1 = *(const float4*)(h + c + 4);
                float4 w2 = *(const float4*)(w + c + 8);
                float4 h2 = *(const float4*)(h + c + 8);
                float4 w3 = *(const float4*)(w + c + 12);
                float4 h3 = *(const float4*)(h + c + 12);
                a0 = fmaf(w0.x, h0.x, a0); a0 = fmaf(w0.y, h0.y, a0);
                a0 = fmaf(w0.z, h0.z, a0); a0 = fmaf(w0.w, h0.w, a0);
                a1 = fmaf(w1.x, h1.x, a1); a1 = fmaf(w1.y, h1.y, a1);
                a1 = fmaf(w1.z, h1.z, a1); a1 = fmaf(w1.w, h1.w, a1);
                a2 = fmaf(w2.x, h2.x, a2); a2 = fmaf(w2.y, h2.y, a2);
                a2 = fmaf(w2.z, h2.z, a2); a2 = fmaf(w2.w, h2.w, a2);
                a3 = fmaf(w3.x, h3.x, a3); a3 = fmaf(w3.y, h3.y, a3);
                a3 = fmaf(w3.z, h3.z, a3); a3 = fmaf(w3.w, h3.w, a3);
            }
            ts[tok][j] = ((a0 + a1) + (a2 + a3)) + b_out[j];
        }
    }
    __syncthreads();

    // warp w: log_softmax for token w (lanes cover j and j+32)
    const int wrp  = tid >> 5;
    const int lane = tid & 31;
    if (wrp < OB_TOK) {
        const float v0 = (lane      < T_TAGS) ? ts[wrp][lane]      : -1e30f;
        const float v1 = (lane + 32 < T_TAGS) ? ts[wrp][lane + 32] : -1e30f;
        float mx = fmaxf(v0, v1);
#pragma unroll
        for (int off = 16; off; off >>= 1)
            mx = fmaxf(mx, __shfl_xor_sync(0xffffffffu, mx, off));
        float sum = ((lane      < T_TAGS) ? expf(v0 - mx) : 0.f)
                  + ((lane + 32 < T_TAGS) ? expf(v1 - mx) : 0.f);
#pragma unroll
        for (int off = 16; off; off >>= 1)
            sum += __shfl_xor_sync(0xffffffffu, sum, off);
        const float lse = mx + logf(sum);
        float* o = out + (size_t)(s0 + wrp) * T_TAGS;
        if (lane      < T_TAGS) o[lane]      = v0 - lse;
        if (lane + 32 < T_TAGS) o[lane + 32] = v1 - lse;
    }
}

// ---------------- launch ----------------
extern "C" void kernel_launch(void* const* d_in, const int* in_sizes, int n_in,
                              void* d_out, int out_size)
{
    const int*   sent  = (const int*)  d_in[0];
    const float* emb   = (const float*)d_in[1];
    const float* W_ih  = (const float*)d_in[2];
    const float* W_hh  = (const float*)d_in[3];
    const float* b_ih  = (const float*)d_in[4];
    const float* b_hh  = (const float*)d_in[5];
    const float* W_out = (const float*)d_in[6];
    const float* b_out = (const float*)d_in[7];
    const float* h0    = (const float*)d_in[8];
    float* out = (float*)d_out;

    (void)in_sizes; (void)n_in; (void)out_size;

    const size_t rsmem = (size_t)(16384 + 64 + 2 * N_GRP * 16) * sizeof(float);
    cudaFuncSetAttribute(rnn_kernel, cudaFuncAttributeMaxDynamicSharedMemorySize,
                         (int)rsmem);

    init_cnt_kernel<<<1, 256>>>();

    rnn_kernel<<<RB_NBLK, RB_THREADS, rsmem>>>(W_hh, h0, sent, emb,
                                               W_ih, b_ih, b_hh);

    head_kernel<<<S_LEN / OB_TOK, OB_THREADS>>>(W_out, b_out, out);
}